// round 7
// baseline (speedup 1.0000x reference)
#include <cuda_runtime.h>
#include <cuda_bf16.h>

// Cost volume: out[n,c,d,h,w] = left[n,c,h,w] * right[n,c,h,w-d]  (0 if w<d)
// N=2 C=32 H=136 W=240 D=48, fp32.
//
// Config sweep settled on 256thr/8 CTAs/SM (R4 = 59.4us, ~6.75 TB/s writes).
// R7: persistent grid-stride at exactly one full residency (148*8 = 1184
// CTAs) to erase the 7.35-wave tail; each CTA streams ~7 rows back-to-back.
// Inner scheme unchanged: d = 4q+s -> 2 aligned LDS.128 serve 4 disparities;
// STG.128 streaming (__stcs).

#define NW   240
#define NH   136
#define NC   32
#define NN   2
#define ND   48
#define NROWS (NN * NC * NH)   // 8704
#define W4   60                // float4 columns per row
#define PADF 64                // zero floats in front of P
#define ROWSZ (PADF + NW)      // 304
#define THREADS 256
#define GRID  (148 * 8)        // one full residency wave

__global__ __launch_bounds__(THREADS, 8)
void cost_volume_kernel(const float* __restrict__ left,
                        const float* __restrict__ right,
                        float* __restrict__ out) {
    __shared__ __align__(16) float buf[ROWSZ];

    const int tid  = threadIdx.x;
    const int lane = tid & 31;
    const int wid  = tid >> 5;                    // 0..7

    // Warp mapping (fixed across rows): column half + d-stripe.
    const int c      = lane + ((wid & 1) << 5);   // float4 column 0..63
    const int stripe = wid >> 1;                  // 0..3
    const bool act   = (c < W4);

    for (int row = blockIdx.x; row < NROWS; row += GRID) {
        const int h  = row % NH;
        const int nc = row / NH;

        // WAR: previous iteration's smem reads must finish before refill.
        __syncthreads();
        const float* rrow = right + (size_t)row * NW;
        for (int i = tid; i < ROWSZ; i += THREADS)
            buf[i] = (i < PADF) ? 0.0f : rrow[i - PADF];
        __syncthreads();

        if (!act) continue;

        const float4 l4 =
            reinterpret_cast<const float4*>(left + (size_t)row * NW)[c];

        float* obase = out + ((size_t)nc * ND * NH + h) * NW + 4 * c;
        const float* P = buf + PADF;              // P[x], x down to -64 valid

        #pragma unroll
        for (int g = 0; g < 3; g++) {
            const int q = 3 * stripe + g;         // d-group: d = 4q+s, s=0..3
            const float4 Y = *reinterpret_cast<const float4*>(P + 4 * (c - q));
            const float4 X = *reinterpret_cast<const float4*>(P + 4 * (c - q - 1));
            const float yv[4] = {Y.x, Y.y, Y.z, Y.w};
            const float xv[4] = {X.x, X.y, X.z, X.w};

            #pragma unroll
            for (int s = 0; s < 4; s++) {
                const int d = 4 * q + s;
                float4 v;
                // out[4c+i] uses P[4c+i-d] = (i>=s) ? Y[i-s] : X[i+4-s]
                v.x = l4.x * ((0 >= s) ? yv[0] : xv[4 - s]);
                v.y = l4.y * ((1 >= s) ? yv[(1 - s) & 3] : xv[(5 - s) & 3]);
                v.z = l4.z * ((2 >= s) ? yv[(2 - s) & 3] : xv[(6 - s) & 3]);
                v.w = l4.w * ((3 >= s) ? yv[(3 - s) & 3] : xv[(7 - s) & 3]);
                __stcs(reinterpret_cast<float4*>(obase + (size_t)d * (NH * NW)), v);
            }
        }
    }
}

extern "C" void kernel_launch(void* const* d_in, const int* in_sizes, int n_in,
                              void* d_out, int out_size) {
    const float* left  = (const float*)d_in[0];
    const float* right = (const float*)d_in[1];
    float* out = (float*)d_out;

    cost_volume_kernel<<<GRID, THREADS>>>(left, right, out);
}

// round 8
// speedup vs baseline: 1.5293x; 1.5293x over previous
#include <cuda_runtime.h>
#include <cuda_bf16.h>

// Cost volume: out[n,c,d,h,w] = left[n,c,h,w] * right[n,c,h,w-d]  (0 if w<d)
// N=2 C=32 H=136 W=240 D=48, fp32.
//
// R7 lesson: persistent loop + per-row barriers serialize store drain -> 90us.
// Revert to R4 champion (8704 CTAs, 256 thr, 8/SM, 59.4us) + wavefront fix:
// row stride 960B = 7.5 lines, so odd-h rows start at 64 mod 128. Splitting
// the two half-row warps at column 28 (odd h) instead of 32 realigns the
// second warp's 512B store to a line boundary: 9 -> 8 wavefronts per odd row.

#define NW   240
#define NH   136
#define NC   32
#define NN   2
#define ND   48
#define W4   60              // float4 columns per row
#define PADF 64              // zero floats in front of P
#define ROWSZ (PADF + NW)    // 304
#define THREADS 256

__global__ __launch_bounds__(THREADS, 8)
void cost_volume_kernel(const float* __restrict__ left,
                        const float* __restrict__ right,
                        float* __restrict__ out) {
    // buf[i] = P[i - PADF]; P[x] = rrow[x] for 0<=x<240, 0 for x<0.
    __shared__ __align__(16) float buf[ROWSZ];

    const int row  = blockIdx.x;         // row = nc * NH + h
    const int h    = row % NH;
    const int nc   = row / NH;
    const int tid  = threadIdx.x;
    const int lane = tid & 31;
    const int wid  = tid >> 5;           // 0..7

    const float* rrow = right + (size_t)row * NW;
    for (int i = tid; i < ROWSZ; i += THREADS)
        buf[i] = (i < PADF) ? 0.0f : rrow[i - PADF];
    __syncthreads();

    // 8 warps: [wid&1] selects column chunk, [wid>>1] selects d-stripe.
    // Line-aligned split: even h rows are 128B-aligned -> split at 32;
    // odd h rows start at 64 mod 128 -> split at 28 so the upper warp's
    // 512B store lands line-aligned (8 wavefronts/row instead of 9).
    const int split  = 32 - ((h & 1) << 2);       // 32 or 28
    const int half   = wid & 1;
    const int c      = lane + (half ? split : 0); // float4 column
    const int stripe = wid >> 1;                  // 0..3
    // Active: lower warp covers [0, split), upper [split, 60).
    if (half ? (c >= W4) : (lane >= split)) return;  // no collectives below

    const float4 l4 = reinterpret_cast<const float4*>(left + (size_t)row * NW)[c];

    float* obase = out + ((size_t)nc * ND * NH + h) * NW + 4 * c;
    const float* P = buf + PADF;                  // P[x], x down to -64 valid

    #pragma unroll
    for (int g = 0; g < 3; g++) {
        const int q = 3 * stripe + g;             // d-group: d = 4q+s, s=0..3
        // Two aligned 16B smem loads cover all 4 disparities of this group.
        const float4 Y = *reinterpret_cast<const float4*>(P + 4 * (c - q));
        const float4 X = *reinterpret_cast<const float4*>(P + 4 * (c - q - 1));
        const float yv[4] = {Y.x, Y.y, Y.z, Y.w};
        const float xv[4] = {X.x, X.y, X.z, X.w};

        #pragma unroll
        for (int s = 0; s < 4; s++) {
            const int d = 4 * q + s;
            float4 v;
            // out[4c+i] uses P[4c+i-d] = (i>=s) ? Y[i-s] : X[i+4-s]  (static)
            v.x = l4.x * ((0 >= s) ? yv[0] : xv[4 - s]);
            v.y = l4.y * ((1 >= s) ? yv[(1 - s) & 3] : xv[(5 - s) & 3]);
            v.z = l4.z * ((2 >= s) ? yv[(2 - s) & 3] : xv[(6 - s) & 3]);
            v.w = l4.w * ((3 >= s) ? yv[(3 - s) & 3] : xv[(7 - s) & 3]);
            __stcs(reinterpret_cast<float4*>(obase + (size_t)d * (NH * NW)), v);
        }
    }
}

extern "C" void kernel_launch(void* const* d_in, const int* in_sizes, int n_in,
                              void* d_out, int out_size) {
    const float* left  = (const float*)d_in[0];
    const float* right = (const float*)d_in[1];
    float* out = (float*)d_out;

    const int grid = NN * NC * NH;       // 8704 CTAs, one per (n,c,h) row
    cost_volume_kernel<<<grid, THREADS>>>(left, right, out);
}